// round 6
// baseline (speedup 1.0000x reference)
#include <cuda_runtime.h>

// DropBlock, single fused launch.
// x [64,256,64,64] f32, u [58,58] f32. BLOCK_SIZE=7, DROP_PROB=0.1.
//
// CTA 0 computes the 64x64 multiplier table (bitboards) into d_mult and
// release-publishes d_ready. All other CTAs front-issue their x load
// (independent of the mask), acquire-poll d_ready once per CTA, then
// multiply+store. CTA0 is in wave 1 and never waits -> no deadlock.
// The mask is recomputed identically on every call (deterministic).

#define H 64
#define W 64
#define HW 4096
#define US 58           // H - BS + 1
#define BS 7
#define DROP_PROB 0.1f
#define THREADS 256

__device__ __align__(16) float d_mult[HW];
__device__ int d_ready;   // zero-initialized at module load

__global__ __launch_bounds__(THREADS)
void dropblock_kernel(const float* __restrict__ u,
                      const float4* __restrict__ x4,
                      float4* __restrict__ out4,
                      int n4) {
    int tid = threadIdx.x;
    int idx = blockIdx.x * THREADS + tid;
    bool valid = idx < n4;

    // Front-issue the big global read (mask-independent).
    float4 v;
    if (valid) v = __ldcs(&x4[idx]);

    if (blockIdx.x == 0) {
        // ---- CTA 0: build multiplier table ----
        __shared__ unsigned long long s_drop[US];
        __shared__ unsigned long long s_hdil[US];
        __shared__ unsigned long long s_vdil[H];
        __shared__ int s_sum;

        if (tid < US) s_drop[tid] = 0ULL;
        if (tid == 0) s_sum = 0;
        __syncthreads();

        for (int p = tid; p < US * US; p += THREADS) {
            int i = p / US;
            int j = p - i * US;
            if (__ldg(&u[p]) < DROP_PROB)
                atomicOr(&s_drop[i], 1ULL << j);
        }
        __syncthreads();

        if (tid < US) {
            unsigned long long b = s_drop[tid];
            unsigned long long h = b;
            #pragma unroll
            for (int s = 1; s < BS; s++) h |= b << s;
            s_hdil[tid] = h;
        }
        __syncthreads();

        if (tid < H) {
            int y = tid;
            int i0 = y - (BS - 1); if (i0 < 0) i0 = 0;
            int i1 = y;            if (i1 > US - 1) i1 = US - 1;
            unsigned long long vv = 0ULL;
            for (int i = i0; i <= i1; i++) vv |= s_hdil[i];
            s_vdil[y] = vv;
            int keep = W - __popcll(vv);
            #pragma unroll
            for (int off = 16; off > 0; off >>= 1)
                keep += __shfl_down_sync(0xFFFFFFFFu, keep, off);
            if ((tid & 31) == 0) atomicAdd(&s_sum, keep);
        }
        __syncthreads();

        float scale = (float)HW / (float)s_sum;

        for (int p = tid; p < HW; p += THREADS) {
            int y = p >> 6;
            int x = p & 63;
            d_mult[p] = ((s_vdil[y] >> x) & 1ULL) ? 0.0f : scale;
        }
        // publish: all writes above -> release store of the flag
        __syncthreads();
        if (tid == 0) {
            int one = 1;
            asm volatile("st.global.release.gpu.b32 [%0], %1;"
                         :: "l"(&d_ready), "r"(one) : "memory");
        }
        __syncthreads();   // CTA0's own threads: d_mult writes visible after sync
    } else {
        // ---- consumers: one acquire-poll per CTA ----
        if (tid == 0) {
            int r;
            do {
                asm volatile("ld.global.acquire.gpu.b32 %0, [%1];"
                             : "=r"(r) : "l"(&d_ready) : "memory");
                if (r) break;
                __nanosleep(64);
            } while (true);
        }
        __syncthreads();   // orders the acquire before everyone's d_mult reads
    }

    if (!valid) return;
    const float4* m4 = reinterpret_cast<const float4*>(d_mult);
    float4 m = __ldg(&m4[idx & 1023]);
    v.x *= m.x; v.y *= m.y; v.z *= m.z; v.w *= m.w;
    __stcs(&out4[idx], v);
}

extern "C" void kernel_launch(void* const* d_in, const int* in_sizes, int n_in,
                              void* d_out, int out_size) {
    const float* x = (const float*)d_in[0];
    const float* u = (const float*)d_in[1];
    float* out = (float*)d_out;

    int n4 = out_size / 4;               // 16,777,216 float4s
    int blocks = (n4 + THREADS - 1) / THREADS;
    dropblock_kernel<<<blocks, THREADS>>>(
        u, (const float4*)x, (float4*)out, n4);
}